// round 3
// baseline (speedup 1.0000x reference)
#include <cuda_runtime.h>
#include <math.h>
#include <stdint.h>

#define NMAX 100000
#define EPSBN 1e-5f

// ---------------- scratch (device globals: no allocations allowed) ----------
__device__ float g_agg[(size_t)NMAX * 256];   // aggregation buffer (max width 256)
__device__ float g_h1[(size_t)NMAX * 128];    // layer-1 output
__device__ float g_h2[(size_t)NMAX * 256];    // layer-2 output
__device__ float g_deg[NMAX];
__device__ float g_invdeg[NMAX];

// ---------------- degree histogram ------------------------------------------
__global__ void hist_kernel(const int* __restrict__ dst, int E) {
    int i = blockIdx.x * blockDim.x + threadIdx.x;
    if (i < E) atomicAdd(&g_deg[dst[i]], 1.0f);
}

__global__ void invdeg_kernel(int M) {
    int i = blockIdx.x * blockDim.x + threadIdx.x;
    if (i < M) g_invdeg[i] = 1.0f / fmaxf(g_deg[i], 1.0f);
}

// ---------------- edge scatter: agg[dst] += h[src] --------------------------
// One thread handles one float4 of one edge's row. lanes = d/4 = 1<<lshift.
__global__ void scatter_kernel(const float* __restrict__ h,
                               const int* __restrict__ src,
                               const int* __restrict__ dst,
                               float* __restrict__ agg,
                               int E, int d, int lshift) {
    unsigned idx = blockIdx.x * blockDim.x + threadIdx.x;
    unsigned total = ((unsigned)E) << lshift;
    if (idx >= total) return;
    int e = idx >> lshift;
    int c = (idx & ((1u << lshift) - 1u)) << 2;
    int s = src[e];
    int t = dst[e];
    const float4 v = *(const float4*)(h + (size_t)s * d + c);
    float* p = agg + (size_t)t * d + c;
    // vector reduction (sm_90+): no return value, L2-side add, 16B per op
    asm volatile("red.global.add.v4.f32 [%0], {%1, %2, %3, %4};"
                 :: "l"(p), "f"(v.x), "f"(v.y), "f"(v.z), "f"(v.w)
                 : "memory");
}

// ---------------- fused dual GEMM + bias + ReLU + BN ------------------------
// C[m,n] = BN(ReLU( (agg[m,:]*invdeg[m]) @ Wl + Aself[m,:] @ Wr + bias ))
// Block tile 128x128, BK=8, 256 threads, 8x8 register tile per thread.
template<int K, int NOUT>
__launch_bounds__(256, 2)
__global__ void gemm_fused(const float* __restrict__ Aagg,
                           const float* __restrict__ Aself,
                           const float* __restrict__ Wl,
                           const float* __restrict__ Wr,
                           const float* __restrict__ bias,
                           const float* __restrict__ gam,
                           const float* __restrict__ bet,
                           const float* __restrict__ mu,
                           const float* __restrict__ var,
                           const float* __restrict__ invdeg,
                           float* __restrict__ C, int M) {
    __shared__ float As[8][132];   // transposed A tile, +4 pad
    __shared__ float Ws[8][128];

    const int tid  = threadIdx.x;
    const int row0 = blockIdx.x * 128;
    const int col0 = blockIdx.y * 128;

    // A-tile load mapping: 128 rows x 8 cols, 1 float4 per thread
    const int ar = tid >> 1;
    const int ac = (tid & 1) * 4;
    // W-tile load mapping: 8 rows x 128 cols, 1 float4 per thread
    const int wrow = tid >> 5;
    const int wc   = (tid & 31) * 4;
    // compute mapping: 16x16 thread grid of 8x8 micro-tiles
    const int tm = (tid >> 4) * 8;
    const int tn = (tid & 15) * 8;

    float acc[8][8];
    #pragma unroll
    for (int i = 0; i < 8; i++)
        #pragma unroll
        for (int j = 0; j < 8; j++) acc[i][j] = 0.0f;

    const int  grow    = row0 + ar;
    const bool arow_ok = grow < M;
    const float idg    = arow_ok ? invdeg[grow] : 0.0f;

    #pragma unroll
    for (int phase = 0; phase < 2; ++phase) {
        const float* A = phase ? Aself : Aagg;
        const float* W = phase ? Wr : Wl;
        const float  s = phase ? 1.0f : idg;

        for (int k0 = 0; k0 < K; k0 += 8) {
            float4 av = make_float4(0.f, 0.f, 0.f, 0.f);
            if (arow_ok) av = *(const float4*)(A + (size_t)grow * K + k0 + ac);
            av.x *= s; av.y *= s; av.z *= s; av.w *= s;
            const float4 wv = *(const float4*)(W + (size_t)(k0 + wrow) * NOUT + col0 + wc);

            __syncthreads();
            As[ac + 0][ar] = av.x;
            As[ac + 1][ar] = av.y;
            As[ac + 2][ar] = av.z;
            As[ac + 3][ar] = av.w;
            *(float4*)&Ws[wrow][wc] = wv;
            __syncthreads();

            #pragma unroll
            for (int kk = 0; kk < 8; ++kk) {
                float4 a0 = *(const float4*)&As[kk][tm];
                float4 a1 = *(const float4*)&As[kk][tm + 4];
                float4 b0 = *(const float4*)&Ws[kk][tn];
                float4 b1 = *(const float4*)&Ws[kk][tn + 4];
                const float a[8] = {a0.x, a0.y, a0.z, a0.w, a1.x, a1.y, a1.z, a1.w};
                const float b[8] = {b0.x, b0.y, b0.z, b0.w, b1.x, b1.y, b1.z, b1.w};
                #pragma unroll
                for (int i = 0; i < 8; i++)
                    #pragma unroll
                    for (int j = 0; j < 8; j++)
                        acc[i][j] += a[i] * b[j];
            }
        }
    }

    // epilogue: bias -> ReLU -> BatchNorm(eval)
    float sc[8], sh[8], bb[8];
    #pragma unroll
    for (int j = 0; j < 8; j++) {
        int c = col0 + tn + j;
        float rs = rsqrtf(var[c] + EPSBN);
        sc[j] = gam[c] * rs;
        sh[j] = bet[c] - mu[c] * sc[j];
        bb[j] = bias[c];
    }
    #pragma unroll
    for (int i = 0; i < 8; i++) {
        int r = row0 + tm + i;
        if (r < M) {
            float v[8];
            #pragma unroll
            for (int j = 0; j < 8; j++) {
                float z = acc[i][j] + bb[j];
                z = fmaxf(z, 0.0f);
                v[j] = z * sc[j] + sh[j];
            }
            *(float4*)(C + (size_t)r * NOUT + col0 + tn)     = make_float4(v[0], v[1], v[2], v[3]);
            *(float4*)(C + (size_t)r * NOUT + col0 + tn + 4) = make_float4(v[4], v[5], v[6], v[7]);
        }
    }
}

// ---------------- launcher ---------------------------------------------------
extern "C" void kernel_launch(void* const* d_in, const int* in_sizes, int n_in,
                              void* d_out, int out_size) {
    const float* x   = (const float*)d_in[0];
    const int*   ei  = (const int*)d_in[1];
    const int    E   = in_sizes[1] / 2;
    const int    M   = in_sizes[0] / 128;
    const int*   src = ei;
    const int*   dst = ei + E;

    const float* w1l = (const float*)d_in[2];
    const float* w1r = (const float*)d_in[3];
    const float* b1  = (const float*)d_in[4];
    const float* ga1 = (const float*)d_in[5];
    const float* be1 = (const float*)d_in[6];
    const float* m1  = (const float*)d_in[7];
    const float* v1  = (const float*)d_in[8];
    const float* w2l = (const float*)d_in[9];
    const float* w2r = (const float*)d_in[10];
    const float* b2  = (const float*)d_in[11];
    const float* ga2 = (const float*)d_in[12];
    const float* be2 = (const float*)d_in[13];
    const float* m2  = (const float*)d_in[14];
    const float* v2  = (const float*)d_in[15];
    const float* w3l = (const float*)d_in[16];
    const float* w3r = (const float*)d_in[17];
    const float* b3  = (const float*)d_in[18];
    const float* ga3 = (const float*)d_in[19];
    const float* be3 = (const float*)d_in[20];
    const float* m3  = (const float*)d_in[21];
    const float* v3  = (const float*)d_in[22];

    float* out = (float*)d_out;

    float *agg, *h1, *h2, *deg, *invdeg;
    cudaGetSymbolAddress((void**)&agg,    g_agg);
    cudaGetSymbolAddress((void**)&h1,     g_h1);
    cudaGetSymbolAddress((void**)&h2,     g_h2);
    cudaGetSymbolAddress((void**)&deg,    g_deg);
    cudaGetSymbolAddress((void**)&invdeg, g_invdeg);

    const int T = 256;

    // degrees
    cudaMemsetAsync(deg, 0, (size_t)M * sizeof(float), 0);
    hist_kernel<<<(E + T - 1) / T, T>>>(dst, E);
    invdeg_kernel<<<(M + T - 1) / T, T>>>(M);

    // ---- layer 1: x[*,128] -> h1[*,128]
    cudaMemsetAsync(agg, 0, (size_t)M * 128 * sizeof(float), 0);
    {
        unsigned total = (unsigned)E << 5;   // E * 32 lanes (d=128)
        scatter_kernel<<<(total + T - 1) / T, T>>>(x, src, dst, agg, E, 128, 5);
    }
    {
        dim3 grid((M + 127) / 128, 128 / 128);
        gemm_fused<128, 128><<<grid, T>>>(agg, x, w1l, w1r, b1, ga1, be1, m1, v1,
                                          invdeg, h1, M);
    }

    // ---- layer 2: h1[*,128] -> h2[*,256]
    cudaMemsetAsync(agg, 0, (size_t)M * 128 * sizeof(float), 0);
    {
        unsigned total = (unsigned)E << 5;
        scatter_kernel<<<(total + T - 1) / T, T>>>(h1, src, dst, agg, E, 128, 5);
    }
    {
        dim3 grid((M + 127) / 128, 256 / 128);
        gemm_fused<128, 256><<<grid, T>>>(agg, h1, w2l, w2r, b2, ga2, be2, m2, v2,
                                          invdeg, h2, M);
    }

    // ---- layer 3: h2[*,256] -> out[*,256]
    cudaMemsetAsync(agg, 0, (size_t)M * 256 * sizeof(float), 0);
    {
        unsigned total = (unsigned)E << 6;   // E * 64 lanes (d=256)
        scatter_kernel<<<(total + T - 1) / T, T>>>(h2, src, dst, agg, E, 256, 6);
    }
    {
        dim3 grid((M + 127) / 128, 256 / 128);
        gemm_fused<256, 256><<<grid, T>>>(agg, h2, w3l, w3r, b3, ga3, be3, m3, v3,
                                          invdeg, out, M);
    }
}

// round 4
// speedup vs baseline: 1.4681x; 1.4681x over previous
#include <cuda_runtime.h>
#include <math.h>
#include <stdint.h>

#define NMAX 100000
#define EPSBN 1e-5f

// ---------------- scratch (device globals: no allocations allowed) ----------
__device__ float g_agg[(size_t)NMAX * 256];   // aggregation buffer (max width 256)
__device__ float g_h1[(size_t)NMAX * 128];    // layer-1 output
__device__ float g_h2[(size_t)NMAX * 256];    // layer-2 output
__device__ float g_deg[NMAX];
__device__ float g_invdeg[NMAX];

// ---------------- degree histogram ------------------------------------------
__global__ void hist_kernel(const int* __restrict__ dst, int E) {
    int i = blockIdx.x * blockDim.x + threadIdx.x;
    if (i < E) atomicAdd(&g_deg[dst[i]], 1.0f);
}

__global__ void invdeg_kernel(int M) {
    int i = blockIdx.x * blockDim.x + threadIdx.x;
    if (i < M) g_invdeg[i] = 1.0f / fmaxf(g_deg[i], 1.0f);
}

// ---------------- edge scatter: agg[dst] += h[src] --------------------------
__global__ void scatter_kernel(const float* __restrict__ h,
                               const int* __restrict__ src,
                               const int* __restrict__ dst,
                               float* __restrict__ agg,
                               int E, int d, int lshift) {
    unsigned idx = blockIdx.x * blockDim.x + threadIdx.x;
    unsigned total = ((unsigned)E) << lshift;
    if (idx >= total) return;
    int e = idx >> lshift;
    int c = (idx & ((1u << lshift) - 1u)) << 2;
    int s = src[e];
    int t = dst[e];
    const float4 v = *(const float4*)(h + (size_t)s * d + c);
    float* p = agg + (size_t)t * d + c;
    asm volatile("red.global.add.v4.f32 [%0], {%1, %2, %3, %4};"
                 :: "l"(p), "f"(v.x), "f"(v.y), "f"(v.z), "f"(v.w)
                 : "memory");
}

// ---------------- TF32 helpers -----------------------------------------------
__device__ __forceinline__ unsigned f2tf(float f) {
    unsigned u;
    asm("cvt.rna.tf32.f32 %0, %1;" : "=r"(u) : "f"(f));
    return u;
}

__device__ __forceinline__ void mma_tf32(float* c, const unsigned* a, const unsigned* b) {
    asm volatile(
        "mma.sync.aligned.m16n8k8.row.col.f32.tf32.tf32.f32 "
        "{%0,%1,%2,%3}, {%4,%5,%6,%7}, {%8,%9}, {%0,%1,%2,%3};"
        : "+f"(c[0]), "+f"(c[1]), "+f"(c[2]), "+f"(c[3])
        : "r"(a[0]), "r"(a[1]), "r"(a[2]), "r"(a[3]), "r"(b[0]), "r"(b[1]));
}

// ---------------- fused dual GEMM (tensor cores) + bias + ReLU + BN ----------
// C[m,n] = BN(ReLU( (agg[m,:]*invdeg[m]) @ Wl + Aself[m,:] @ Wr + bias ))
// Block tile 128x128, BK=16, 256 threads (8 warps, 2x4), warp tile 64x32.
template<int K, int NOUT>
__global__ void __launch_bounds__(256, 2)
gemm_tc(const float* __restrict__ Aagg,
        const float* __restrict__ Aself,
        const float* __restrict__ Wl,
        const float* __restrict__ Wr,
        const float* __restrict__ bias,
        const float* __restrict__ gam,
        const float* __restrict__ bet,
        const float* __restrict__ mu,
        const float* __restrict__ var,
        const float* __restrict__ invdeg,
        float* __restrict__ C, int M) {
    __shared__ unsigned As[2][128][20];   // pitch 20: conflict-free A frag reads
    __shared__ unsigned Bs[2][16][136];   // pitch 136: conflict-free B frag reads

    const int tid  = threadIdx.x;
    const int lane = tid & 31;
    const int wid  = tid >> 5;
    const int wm   = wid & 1;          // warp row  (0..1) -> 64 rows
    const int wn   = wid >> 1;         // warp col  (0..3) -> 32 cols
    const int row0 = blockIdx.x * 128;
    const int col0 = blockIdx.y * 128;

    // global load mappings
    const int ar = tid >> 2;           // 0..63 (A rows ar and ar+64)
    const int ac = (tid & 3) << 2;     // 0,4,8,12
    const int br = tid >> 5;           // 0..7  (B rows br and br+8)
    const int bc = lane << 2;          // 0..124

    const int  gr0 = row0 + ar, gr1 = gr0 + 64;
    const bool ok0 = gr0 < M,  ok1 = gr1 < M;
    const float idg0 = ok0 ? invdeg[gr0] : 0.0f;
    const float idg1 = ok1 ? invdeg[gr1] : 0.0f;

    float acc[4][4][4];
    #pragma unroll
    for (int i = 0; i < 4; i++)
        #pragma unroll
        for (int j = 0; j < 4; j++)
            #pragma unroll
            for (int q = 0; q < 4; q++) acc[i][j][q] = 0.0f;

    const int PH  = K / 16;            // iterations per phase
    const int NIT = 2 * PH;

    float4 a0v, a1v, b0v, b1v;

    auto LOAD = [&](int it) {
        const int ph = (it >= PH) ? 1 : 0;
        const int kb = (ph ? it - PH : it) * 16;
        const float* A = ph ? Aself : Aagg;
        const float* W = ph ? Wr : Wl;
        const float s0 = ph ? 1.0f : idg0;
        const float s1 = ph ? 1.0f : idg1;
        a0v = ok0 ? *(const float4*)(A + (size_t)gr0 * K + kb + ac)
                  : make_float4(0.f, 0.f, 0.f, 0.f);
        a1v = ok1 ? *(const float4*)(A + (size_t)gr1 * K + kb + ac)
                  : make_float4(0.f, 0.f, 0.f, 0.f);
        a0v.x *= s0; a0v.y *= s0; a0v.z *= s0; a0v.w *= s0;
        a1v.x *= s1; a1v.y *= s1; a1v.z *= s1; a1v.w *= s1;
        b0v = *(const float4*)(W + (size_t)(kb + br)     * NOUT + col0 + bc);
        b1v = *(const float4*)(W + (size_t)(kb + br + 8) * NOUT + col0 + bc);
    };

    auto STORE = [&](int buf) {
        uint4 u;
        u.x = f2tf(a0v.x); u.y = f2tf(a0v.y); u.z = f2tf(a0v.z); u.w = f2tf(a0v.w);
        *(uint4*)&As[buf][ar][ac] = u;
        u.x = f2tf(a1v.x); u.y = f2tf(a1v.y); u.z = f2tf(a1v.z); u.w = f2tf(a1v.w);
        *(uint4*)&As[buf][ar + 64][ac] = u;
        u.x = f2tf(b0v.x); u.y = f2tf(b0v.y); u.z = f2tf(b0v.z); u.w = f2tf(b0v.w);
        *(uint4*)&Bs[buf][br][bc] = u;
        u.x = f2tf(b1v.x); u.y = f2tf(b1v.y); u.z = f2tf(b1v.z); u.w = f2tf(b1v.w);
        *(uint4*)&Bs[buf][br + 8][bc] = u;
    };

    const int fr = lane >> 2;          // fragment row / B col
    const int fc = lane & 3;           // fragment k col

    auto COMPUTE = [&](int buf) {
        #pragma unroll
        for (int ks = 0; ks < 2; ++ks) {
            const int kk = ks * 8;
            unsigned af[4][4], bf[4][2];
            #pragma unroll
            for (int mi = 0; mi < 4; mi++) {
                const int rb = wm * 64 + mi * 16;
                af[mi][0] = As[buf][rb + fr][kk + fc];
                af[mi][1] = As[buf][rb + fr + 8][kk + fc];
                af[mi][2] = As[buf][rb + fr][kk + fc + 4];
                af[mi][3] = As[buf][rb + fr + 8][kk + fc + 4];
            }
            #pragma unroll
            for (int ni = 0; ni < 4; ni++) {
                const int cb = wn * 32 + ni * 8 + fr;
                bf[ni][0] = Bs[buf][kk + fc][cb];
                bf[ni][1] = Bs[buf][kk + fc + 4][cb];
            }
            #pragma unroll
            for (int mi = 0; mi < 4; mi++)
                #pragma unroll
                for (int ni = 0; ni < 4; ni++)
                    mma_tf32(acc[mi][ni], af[mi], bf[ni]);
        }
    };

    LOAD(0);
    STORE(0);
    __syncthreads();
    for (int it = 0; it < NIT; ++it) {
        const int buf = it & 1;
        if (it + 1 < NIT) LOAD(it + 1);
        COMPUTE(buf);
        if (it + 1 < NIT) {
            __syncthreads();
            STORE((it + 1) & 1);
            __syncthreads();
        }
    }

    // epilogue: bias -> ReLU -> BatchNorm(eval)
    float sc[4][2], sh[4][2], bb[4][2];
    int   cbs[4];
    #pragma unroll
    for (int ni = 0; ni < 4; ni++) {
        const int cb = col0 + wn * 32 + ni * 8 + ((lane & 3) << 1);
        cbs[ni] = cb;
        #pragma unroll
        for (int j = 0; j < 2; j++) {
            const int c = cb + j;
            const float rs = rsqrtf(var[c] + EPSBN);
            sc[ni][j] = gam[c] * rs;
            sh[ni][j] = bet[c] - mu[c] * sc[ni][j];
            bb[ni][j] = bias[c];
        }
    }
    #pragma unroll
    for (int mi = 0; mi < 4; mi++) {
        const int rbase = row0 + wm * 64 + mi * 16 + (lane >> 2);
        #pragma unroll
        for (int h = 0; h < 2; h++) {
            const int r = rbase + h * 8;
            if (r < M) {
                #pragma unroll
                for (int ni = 0; ni < 4; ni++) {
                    float z0 = acc[mi][ni][h * 2 + 0] + bb[ni][0];
                    float z1 = acc[mi][ni][h * 2 + 1] + bb[ni][1];
                    z0 = fmaxf(z0, 0.0f);
                    z1 = fmaxf(z1, 0.0f);
                    float2 o;
                    o.x = z0 * sc[ni][0] + sh[ni][0];
                    o.y = z1 * sc[ni][1] + sh[ni][1];
                    *(float2*)(C + (size_t)r * NOUT + cbs[ni]) = o;
                }
            }
        }
    }
}

// ---------------- launcher ---------------------------------------------------
extern "C" void kernel_launch(void* const* d_in, const int* in_sizes, int n_in,
                              void* d_out, int out_size) {
    const float* x   = (const float*)d_in[0];
    const int*   ei  = (const int*)d_in[1];
    const int    E   = in_sizes[1] / 2;
    const int    M   = in_sizes[0] / 128;
    const int*   src = ei;
    const int*   dst = ei + E;

    const float* w1l = (const float*)d_in[2];
    const float* w1r = (const float*)d_in[3];
    const float* b1  = (const float*)d_in[4];
    const float* ga1 = (const float*)d_in[5];
    const float* be1 = (const float*)d_in[6];
    const float* m1  = (const float*)d_in[7];
    const float* v1  = (const float*)d_in[8];
    const float* w2l = (const float*)d_in[9];
    const float* w2r = (const float*)d_in[10];
    const float* b2  = (const float*)d_in[11];
    const float* ga2 = (const float*)d_in[12];
    const float* be2 = (const float*)d_in[13];
    const float* m2  = (const float*)d_in[14];
    const float* v2  = (const float*)d_in[15];
    const float* w3l = (const float*)d_in[16];
    const float* w3r = (const float*)d_in[17];
    const float* b3  = (const float*)d_in[18];
    const float* ga3 = (const float*)d_in[19];
    const float* be3 = (const float*)d_in[20];
    const float* m3  = (const float*)d_in[21];
    const float* v3  = (const float*)d_in[22];

    float* out = (float*)d_out;

    float *agg, *h1, *h2, *deg, *invdeg;
    cudaGetSymbolAddress((void**)&agg,    g_agg);
    cudaGetSymbolAddress((void**)&h1,     g_h1);
    cudaGetSymbolAddress((void**)&h2,     g_h2);
    cudaGetSymbolAddress((void**)&deg,    g_deg);
    cudaGetSymbolAddress((void**)&invdeg, g_invdeg);

    const int T = 256;

    // degrees
    cudaMemsetAsync(deg, 0, (size_t)M * sizeof(float), 0);
    hist_kernel<<<(E + T - 1) / T, T>>>(dst, E);
    invdeg_kernel<<<(M + T - 1) / T, T>>>(M);

    // ---- layer 1: x[*,128] -> h1[*,128]
    cudaMemsetAsync(agg, 0, (size_t)M * 128 * sizeof(float), 0);
    {
        unsigned total = (unsigned)E << 5;
        scatter_kernel<<<(total + T - 1) / T, T>>>(x, src, dst, agg, E, 128, 5);
    }
    {
        dim3 grid((M + 127) / 128, 1);
        gemm_tc<128, 128><<<grid, T>>>(agg, x, w1l, w1r, b1, ga1, be1, m1, v1,
                                       invdeg, h1, M);
    }

    // ---- layer 2: h1[*,128] -> h2[*,256]
    cudaMemsetAsync(agg, 0, (size_t)M * 128 * sizeof(float), 0);
    {
        unsigned total = (unsigned)E << 5;
        scatter_kernel<<<(total + T - 1) / T, T>>>(h1, src, dst, agg, E, 128, 5);
    }
    {
        dim3 grid((M + 127) / 128, 2);
        gemm_tc<128, 256><<<grid, T>>>(agg, h1, w2l, w2r, b2, ga2, be2, m2, v2,
                                       invdeg, h2, M);
    }

    // ---- layer 3: h2[*,256] -> out[*,256]
    cudaMemsetAsync(agg, 0, (size_t)M * 256 * sizeof(float), 0);
    {
        unsigned total = (unsigned)E << 6;
        scatter_kernel<<<(total + T - 1) / T, T>>>(h2, src, dst, agg, E, 256, 6);
    }
    {
        dim3 grid((M + 127) / 128, 2);
        gemm_tc<256, 256><<<grid, T>>>(agg, h2, w3l, w3r, b3, ga3, be3, m3, v3,
                                       invdeg, out, M);
    }
}

// round 5
// speedup vs baseline: 2.2935x; 1.5622x over previous
#include <cuda_runtime.h>
#include <math.h>
#include <stdint.h>

#define NMAX 100000
#define EMAX 2000000
#define EPSBN 1e-5f

// ---------------- scratch (device globals: no allocations allowed) ----------
__device__ float g_agg[(size_t)NMAX * 256];   // aggregation buffer (max width 256)
__device__ float g_h1[(size_t)NMAX * 128];    // layer-1 output
__device__ float g_h2[(size_t)NMAX * 256];    // layer-2 output
__device__ int   g_cnt[NMAX];
__device__ int   g_off[NMAX + 1];
__device__ int   g_cur[NMAX];
__device__ int   g_csr[EMAX];
__device__ float g_invdeg[NMAX];

// ---------------- CSR build --------------------------------------------------
__global__ void hist_kernel(const int* __restrict__ dst, int E) {
    int i = blockIdx.x * blockDim.x + threadIdx.x;
    if (i < E) atomicAdd(&g_cnt[dst[i]], 1);
}

// single-block exclusive scan over node counts (+ invdeg + cursor init)
__global__ void scan_kernel(int M) {
    __shared__ int part[1024];
    const int t = threadIdx.x;
    const int chunk = (M + 1023) >> 10;
    const int beg = t * chunk;
    const int end = min(beg + chunk, M);
    int s = 0;
    for (int i = beg; i < end; i++) s += g_cnt[i];
    part[t] = s;
    __syncthreads();
    // Hillis-Steele inclusive scan over 1024 partials
    for (int ofs = 1; ofs < 1024; ofs <<= 1) {
        int v = (t >= ofs) ? part[t - ofs] : 0;
        __syncthreads();
        part[t] += v;
        __syncthreads();
    }
    int run = (t > 0) ? part[t - 1] : 0;  // exclusive prefix of this chunk
    for (int i = beg; i < end; i++) {
        g_off[i] = run;
        g_cur[i] = run;
        g_invdeg[i] = 1.0f / fmaxf((float)g_cnt[i], 1.0f);
        run += g_cnt[i];
    }
    if (end == M) g_off[M] = run;  // == E (consistent across writers)
}

__global__ void fill_kernel(const int* __restrict__ src,
                            const int* __restrict__ dst, int E) {
    int i = blockIdx.x * blockDim.x + threadIdx.x;
    if (i < E) {
        int d = dst[i];
        int pos = atomicAdd(&g_cur[d], 1);
        g_csr[pos] = src[i];
    }
}

// ---------------- CSR gather: agg[n,:] = mean_{s in N(n)} h[s,:] -------------
// One warp per node. Coalesced full-row reads per neighbor; one write per node.
template<int D>
__global__ void gather_kernel(const float* __restrict__ h,
                              float* __restrict__ agg, int M) {
    const int warp = (blockIdx.x * blockDim.x + threadIdx.x) >> 5;
    const int lane = threadIdx.x & 31;
    if (warp >= M) return;
    const int beg = g_off[warp];
    const int end = g_off[warp + 1];

    float4 a0 = make_float4(0.f, 0.f, 0.f, 0.f);
    float4 a1 = make_float4(0.f, 0.f, 0.f, 0.f);

    for (int j0 = beg; j0 < end; j0 += 32) {
        const int myi = (j0 + lane < end) ? g_csr[j0 + lane] : 0;
        const int cnt = min(32, end - j0);
        for (int t = 0; t < cnt; t++) {
            const int s = __shfl_sync(0xffffffffu, myi, t);
            const float4* row = (const float4*)(h + (size_t)s * D);
            const float4 v = row[lane];
            a0.x += v.x; a0.y += v.y; a0.z += v.z; a0.w += v.w;
            if (D == 256) {
                const float4 w = row[lane + 32];
                a1.x += w.x; a1.y += w.y; a1.z += w.z; a1.w += w.w;
            }
        }
    }
    const float s = g_invdeg[warp];
    a0.x *= s; a0.y *= s; a0.z *= s; a0.w *= s;
    float4* outr = (float4*)(agg + (size_t)warp * D);
    outr[lane] = a0;
    if (D == 256) {
        a1.x *= s; a1.y *= s; a1.z *= s; a1.w *= s;
        outr[lane + 32] = a1;
    }
}

// ---------------- TF32 helpers -----------------------------------------------
__device__ __forceinline__ unsigned f2tf(float f) {
    unsigned u;
    asm("cvt.rna.tf32.f32 %0, %1;" : "=r"(u) : "f"(f));
    return u;
}

__device__ __forceinline__ void mma_tf32(float* c, const unsigned* a, const unsigned* b) {
    asm volatile(
        "mma.sync.aligned.m16n8k8.row.col.f32.tf32.tf32.f32 "
        "{%0,%1,%2,%3}, {%4,%5,%6,%7}, {%8,%9}, {%0,%1,%2,%3};"
        : "+f"(c[0]), "+f"(c[1]), "+f"(c[2]), "+f"(c[3])
        : "r"(a[0]), "r"(a[1]), "r"(a[2]), "r"(a[3]), "r"(b[0]), "r"(b[1]));
}

// ---------------- fused dual GEMM (tensor cores) + bias + ReLU + BN ----------
// C[m,n] = BN(ReLU( Aagg[m,:] @ Wl + Aself[m,:] @ Wr + bias ))   (Aagg pre-meaned)
// Block tile 128x128, BK=16, 256 threads (8 warps, 2x4), warp tile 64x32.
template<int K, int NOUT>
__global__ void __launch_bounds__(256, 2)
gemm_tc(const float* __restrict__ Aagg,
        const float* __restrict__ Aself,
        const float* __restrict__ Wl,
        const float* __restrict__ Wr,
        const float* __restrict__ bias,
        const float* __restrict__ gam,
        const float* __restrict__ bet,
        const float* __restrict__ mu,
        const float* __restrict__ var,
        float* __restrict__ C, int M) {
    __shared__ unsigned As[2][128][20];   // pitch 20: conflict-free A frag reads
    __shared__ unsigned Bs[2][16][136];   // pitch 136: conflict-free B frag reads

    const int tid  = threadIdx.x;
    const int lane = tid & 31;
    const int wid  = tid >> 5;
    const int wm   = wid & 1;          // warp row  (0..1) -> 64 rows
    const int wn   = wid >> 1;         // warp col  (0..3) -> 32 cols
    const int row0 = blockIdx.x * 128;
    const int col0 = blockIdx.y * 128;

    // global load mappings
    const int ar = tid >> 2;           // 0..63 (A rows ar and ar+64)
    const int ac = (tid & 3) << 2;     // 0,4,8,12
    const int br = tid >> 5;           // 0..7  (B rows br and br+8)
    const int bc = lane << 2;          // 0..124

    const int  gr0 = row0 + ar, gr1 = gr0 + 64;
    const bool ok0 = gr0 < M,  ok1 = gr1 < M;

    float acc[4][4][4];
    #pragma unroll
    for (int i = 0; i < 4; i++)
        #pragma unroll
        for (int j = 0; j < 4; j++)
            #pragma unroll
            for (int q = 0; q < 4; q++) acc[i][j][q] = 0.0f;

    const int PH  = K / 16;            // iterations per phase
    const int NIT = 2 * PH;

    float4 a0v, a1v, b0v, b1v;

    auto LOAD = [&](int it) {
        const int ph = (it >= PH) ? 1 : 0;
        const int kb = (ph ? it - PH : it) * 16;
        const float* A = ph ? Aself : Aagg;
        const float* W = ph ? Wr : Wl;
        a0v = ok0 ? *(const float4*)(A + (size_t)gr0 * K + kb + ac)
                  : make_float4(0.f, 0.f, 0.f, 0.f);
        a1v = ok1 ? *(const float4*)(A + (size_t)gr1 * K + kb + ac)
                  : make_float4(0.f, 0.f, 0.f, 0.f);
        b0v = *(const float4*)(W + (size_t)(kb + br)     * NOUT + col0 + bc);
        b1v = *(const float4*)(W + (size_t)(kb + br + 8) * NOUT + col0 + bc);
    };

    auto STORE = [&](int buf) {
        uint4 u;
        u.x = f2tf(a0v.x); u.y = f2tf(a0v.y); u.z = f2tf(a0v.z); u.w = f2tf(a0v.w);
        *(uint4*)&As[buf][ar][ac] = u;
        u.x = f2tf(a1v.x); u.y = f2tf(a1v.y); u.z = f2tf(a1v.z); u.w = f2tf(a1v.w);
        *(uint4*)&As[buf][ar + 64][ac] = u;
        u.x = f2tf(b0v.x); u.y = f2tf(b0v.y); u.z = f2tf(b0v.z); u.w = f2tf(b0v.w);
        *(uint4*)&Bs[buf][br][bc] = u;
        u.x = f2tf(b1v.x); u.y = f2tf(b1v.y); u.z = f2tf(b1v.z); u.w = f2tf(b1v.w);
        *(uint4*)&Bs[buf][br + 8][bc] = u;
    };

    const int fr = lane >> 2;          // fragment row / B col
    const int fc = lane & 3;           // fragment k col

    auto COMPUTE = [&](int buf) {
        #pragma unroll
        for (int ks = 0; ks < 2; ++ks) {
            const int kk = ks * 8;
            unsigned af[4][4], bf[4][2];
            #pragma unroll
            for (int mi = 0; mi < 4; mi++) {
                const int rb = wm * 64 + mi * 16;
                af[mi][0] = As[buf][rb + fr][kk + fc];
                af[mi][1] = As[buf][rb + fr + 8][kk + fc];
                af[mi][2] = As[buf][rb + fr][kk + fc + 4];
                af[mi][3] = As[buf][rb + fr + 8][kk + fc + 4];
            }
            #pragma unroll
            for (int ni = 0; ni < 4; ni++) {
                const int cb = wn * 32 + ni * 8 + fr;
                bf[ni][0] = Bs[buf][kk + fc][cb];
                bf[ni][1] = Bs[buf][kk + fc + 4][cb];
            }
            #pragma unroll
            for (int mi = 0; mi < 4; mi++)
                #pragma unroll
                for (int ni = 0; ni < 4; ni++)
                    mma_tf32(acc[mi][ni], af[mi], bf[ni]);
        }
    };

    LOAD(0);
    STORE(0);
    __syncthreads();
    for (int it = 0; it < NIT; ++it) {
        const int buf = it & 1;
        if (it + 1 < NIT) LOAD(it + 1);
        COMPUTE(buf);
        if (it + 1 < NIT) {
            __syncthreads();
            STORE((it + 1) & 1);
            __syncthreads();
        }
    }

    // epilogue: bias -> ReLU -> BatchNorm(eval)
    float sc[4][2], sh[4][2], bb[4][2];
    int   cbs[4];
    #pragma unroll
    for (int ni = 0; ni < 4; ni++) {
        const int cb = col0 + wn * 32 + ni * 8 + ((lane & 3) << 1);
        cbs[ni] = cb;
        #pragma unroll
        for (int j = 0; j < 2; j++) {
            const int c = cb + j;
            const float rs = rsqrtf(var[c] + EPSBN);
            sc[ni][j] = gam[c] * rs;
            sh[ni][j] = bet[c] - mu[c] * sc[ni][j];
            bb[ni][j] = bias[c];
        }
    }
    #pragma unroll
    for (int mi = 0; mi < 4; mi++) {
        const int rbase = row0 + wm * 64 + mi * 16 + (lane >> 2);
        #pragma unroll
        for (int h = 0; h < 2; h++) {
            const int r = rbase + h * 8;
            if (r < M) {
                #pragma unroll
                for (int ni = 0; ni < 4; ni++) {
                    float z0 = acc[mi][ni][h * 2 + 0] + bb[ni][0];
                    float z1 = acc[mi][ni][h * 2 + 1] + bb[ni][1];
                    z0 = fmaxf(z0, 0.0f);
                    z1 = fmaxf(z1, 0.0f);
                    float2 o;
                    o.x = z0 * sc[ni][0] + sh[ni][0];
                    o.y = z1 * sc[ni][1] + sh[ni][1];
                    *(float2*)(C + (size_t)r * NOUT + cbs[ni]) = o;
                }
            }
        }
    }
}

// ---------------- launcher ---------------------------------------------------
extern "C" void kernel_launch(void* const* d_in, const int* in_sizes, int n_in,
                              void* d_out, int out_size) {
    const float* x   = (const float*)d_in[0];
    const int*   ei  = (const int*)d_in[1];
    const int    E   = in_sizes[1] / 2;
    const int    M   = in_sizes[0] / 128;
    const int*   src = ei;
    const int*   dst = ei + E;

    const float* w1l = (const float*)d_in[2];
    const float* w1r = (const float*)d_in[3];
    const float* b1  = (const float*)d_in[4];
    const float* ga1 = (const float*)d_in[5];
    const float* be1 = (const float*)d_in[6];
    const float* m1  = (const float*)d_in[7];
    const float* v1  = (const float*)d_in[8];
    const float* w2l = (const float*)d_in[9];
    const float* w2r = (const float*)d_in[10];
    const float* b2  = (const float*)d_in[11];
    const float* ga2 = (const float*)d_in[12];
    const float* be2 = (const float*)d_in[13];
    const float* m2  = (const float*)d_in[14];
    const float* v2  = (const float*)d_in[15];
    const float* w3l = (const float*)d_in[16];
    const float* w3r = (const float*)d_in[17];
    const float* b3  = (const float*)d_in[18];
    const float* ga3 = (const float*)d_in[19];
    const float* be3 = (const float*)d_in[20];
    const float* m3  = (const float*)d_in[21];
    const float* v3  = (const float*)d_in[22];

    float* out = (float*)d_out;

    float *agg, *h1, *h2;
    int   *cnt;
    cudaGetSymbolAddress((void**)&agg, g_agg);
    cudaGetSymbolAddress((void**)&h1,  g_h1);
    cudaGetSymbolAddress((void**)&h2,  g_h2);
    cudaGetSymbolAddress((void**)&cnt, g_cnt);

    const int T = 256;

    // ---- CSR build (dst-sorted adjacency) ----
    cudaMemsetAsync(cnt, 0, (size_t)M * sizeof(int), 0);
    hist_kernel<<<(E + T - 1) / T, T>>>(dst, E);
    scan_kernel<<<1, 1024>>>(M);
    fill_kernel<<<(E + T - 1) / T, T>>>(src, dst, E);

    const int gwarps = (M * 32 + T - 1) / T;   // one warp per node

    // ---- layer 1: x[*,128] -> h1[*,128]
    gather_kernel<128><<<gwarps, T>>>(x, agg, M);
    {
        dim3 grid((M + 127) / 128, 1);
        gemm_tc<128, 128><<<grid, T>>>(agg, x, w1l, w1r, b1, ga1, be1, m1, v1, h1, M);
    }

    // ---- layer 2: h1[*,128] -> h2[*,256]
    gather_kernel<128><<<gwarps, T>>>(h1, agg, M);
    {
        dim3 grid((M + 127) / 128, 2);
        gemm_tc<128, 256><<<grid, T>>>(agg, h1, w2l, w2r, b2, ga2, be2, m2, v2, h2, M);
    }

    // ---- layer 3: h2[*,256] -> out[*,256]
    gather_kernel<256><<<gwarps, T>>>(h2, agg, M);
    {
        dim3 grid((M + 127) / 128, 2);
        gemm_tc<256, 256><<<grid, T>>>(agg, h2, w3l, w3r, b3, ga3, be3, m3, v3, out, M);
    }
}

// round 8
// speedup vs baseline: 2.4338x; 1.0612x over previous
#include <cuda_runtime.h>
#include <math.h>
#include <stdint.h>

#define NMAX 100000
#define EMAX 2000000
#define EPSBN 1e-5f

// ---------------- scratch (device globals: no allocations allowed) ----------
__device__ float g_agg[(size_t)NMAX * 256];   // aggregation buffer (max width 256)
__device__ float g_h1[(size_t)NMAX * 128];    // layer-1 output
__device__ float g_h2[(size_t)NMAX * 256];    // layer-2 output
__device__ int   g_cnt[NMAX];
__device__ int   g_off[NMAX + 1];
__device__ int   g_cur[NMAX];
__device__ int   g_csr[EMAX];
__device__ float g_invdeg[NMAX];

// ---------------- CSR build --------------------------------------------------
__global__ void hist_kernel(const int* __restrict__ dst, int E) {
    int i = blockIdx.x * blockDim.x + threadIdx.x;
    if (i < E) atomicAdd(&g_cnt[dst[i]], 1);
}

// single-block exclusive scan over node counts (+ invdeg + cursor init)
__global__ void scan_kernel(int M) {
    __shared__ int part[1024];
    const int t = threadIdx.x;
    const int chunk = (M + 1023) >> 10;
    const int beg = t * chunk;
    const int end = min(beg + chunk, M);
    int s = 0;
    for (int i = beg; i < end; i++) s += g_cnt[i];
    part[t] = s;
    __syncthreads();
    for (int ofs = 1; ofs < 1024; ofs <<= 1) {
        int v = (t >= ofs) ? part[t - ofs] : 0;
        __syncthreads();
        part[t] += v;
        __syncthreads();
    }
    int run = (t > 0) ? part[t - 1] : 0;
    for (int i = beg; i < end; i++) {
        g_off[i] = run;
        g_cur[i] = run;
        g_invdeg[i] = 1.0f / fmaxf((float)g_cnt[i], 1.0f);
        run += g_cnt[i];
    }
    if (end == M) g_off[M] = run;
}

__global__ void fill_kernel(const int* __restrict__ src,
                            const int* __restrict__ dst, int E) {
    int i = blockIdx.x * blockDim.x + threadIdx.x;
    if (i < E) {
        int d = dst[i];
        int pos = atomicAdd(&g_cur[d], 1);
        g_csr[pos] = src[i];
    }
}

// ---------------- CSR gather: agg[n,:] = mean_{s in N(n)} h[s,:] -------------
template<int D>
__global__ void gather_kernel(const float* __restrict__ h,
                              float* __restrict__ agg, int M) {
    const int warp = (blockIdx.x * blockDim.x + threadIdx.x) >> 5;
    const int lane = threadIdx.x & 31;
    if (warp >= M) return;
    const int beg = g_off[warp];
    const int end = g_off[warp + 1];

    float4 a0 = make_float4(0.f, 0.f, 0.f, 0.f);
    float4 a1 = make_float4(0.f, 0.f, 0.f, 0.f);

    for (int j0 = beg; j0 < end; j0 += 32) {
        const int myi = (j0 + lane < end) ? g_csr[j0 + lane] : 0;
        const int cnt = min(32, end - j0);
        for (int t = 0; t < cnt; t++) {
            const int s = __shfl_sync(0xffffffffu, myi, t);
            const float4* row = (const float4*)(h + (size_t)s * D);
            const float4 v = row[lane];
            a0.x += v.x; a0.y += v.y; a0.z += v.z; a0.w += v.w;
            if (D == 256) {
                const float4 w = row[lane + 32];
                a1.x += w.x; a1.y += w.y; a1.z += w.z; a1.w += w.w;
            }
        }
    }
    const float s = g_invdeg[warp];
    a0.x *= s; a0.y *= s; a0.z *= s; a0.w *= s;
    float4* outr = (float4*)(agg + (size_t)warp * D);
    outr[lane] = a0;
    if (D == 256) {
        a1.x *= s; a1.y *= s; a1.z *= s; a1.w *= s;
        outr[lane + 32] = a1;
    }
}

// ---------------- TF32 / cp.async helpers ------------------------------------
__device__ __forceinline__ unsigned f2tf(float f) {
    unsigned u;
    asm("cvt.rna.tf32.f32 %0, %1;" : "=r"(u) : "f"(f));
    return u;
}

__device__ __forceinline__ void mma_tf32(float* c, const unsigned* a, const unsigned* b) {
    asm volatile(
        "mma.sync.aligned.m16n8k8.row.col.f32.tf32.tf32.f32 "
        "{%0,%1,%2,%3}, {%4,%5,%6,%7}, {%8,%9}, {%0,%1,%2,%3};"
        : "+f"(c[0]), "+f"(c[1]), "+f"(c[2]), "+f"(c[3])
        : "r"(a[0]), "r"(a[1]), "r"(a[2]), "r"(a[3]), "r"(b[0]), "r"(b[1]));
}

__device__ __forceinline__ void cp16(void* dst, const void* src) {
    unsigned d = (unsigned)__cvta_generic_to_shared(dst);
    asm volatile("cp.async.cg.shared.global [%0], [%1], 16;" :: "r"(d), "l"(src));
}
__device__ __forceinline__ void cp_commit() {
    asm volatile("cp.async.commit_group;");
}
template<int N>
__device__ __forceinline__ void cp_wait() {
    asm volatile("cp.async.wait_group %0;" :: "n"(N));
}

// ---------------- fused dual GEMM (TC, cp.async 4-stage) + bias/ReLU/BN ------
// C[m,n] = BN(ReLU( Aagg[m,:] @ Wl + Aself[m,:] @ Wr + bias ))   (Aagg pre-meaned)
// Block 128x128, BK=16, 256 threads (8 warps, 2x4), warp tile 64x32.
#define STAGES 4

template<int K, int NOUT>
__global__ void __launch_bounds__(256, 2)
gemm_tc(const float* __restrict__ Aagg,
        const float* __restrict__ Aself,
        const float* __restrict__ Wl,
        const float* __restrict__ Wr,
        const float* __restrict__ bias,
        const float* __restrict__ gam,
        const float* __restrict__ bet,
        const float* __restrict__ mu,
        const float* __restrict__ var,
        float* __restrict__ C, int M) {
    __shared__ float As[STAGES][128][20];   // pitch 20: conflict-free frag reads
    __shared__ float Bs[STAGES][16][136];   // pitch 136: conflict-free frag reads

    const int tid  = threadIdx.x;
    const int lane = tid & 31;
    const int wid  = tid >> 5;
    const int wm   = wid & 1;          // warp row (0..1) -> 64 rows
    const int wn   = wid >> 1;         // warp col (0..3) -> 32 cols
    const int row0 = blockIdx.x * 128;
    const int col0 = blockIdx.y * 128;

    // global load mappings (cp.async, 16B per op)
    const int ar = tid >> 2;           // 0..63 (rows ar, ar+64)
    const int ac = (tid & 3) << 2;     // 0,4,8,12
    const int br = tid >> 5;           // 0..7  (rows br, br+8)
    const int bc = lane << 2;          // 0..124

    // clamp OOB rows: garbage accumulates into rows that are never stored
    const int gr0 = min(row0 + ar, M - 1);
    const int gr1 = min(row0 + ar + 64, M - 1);

    float acc[4][4][4];
    #pragma unroll
    for (int i = 0; i < 4; i++)
        #pragma unroll
        for (int j = 0; j < 4; j++)
            #pragma unroll
            for (int q = 0; q < 4; q++) acc[i][j][q] = 0.0f;

    const int PH  = K / 16;
    const int NIT = 2 * PH;

    auto ISSUE = [&](int it, int st) {
        const int ph = (it >= PH) ? 1 : 0;
        const int kb = (ph ? it - PH : it) * 16;
        const float* A = ph ? Aself : Aagg;
        const float* W = ph ? Wr : Wl;
        cp16(&As[st][ar][ac],      A + (size_t)gr0 * K + kb + ac);
        cp16(&As[st][ar + 64][ac], A + (size_t)gr1 * K + kb + ac);
        cp16(&Bs[st][br][bc],      W + (size_t)(kb + br)     * NOUT + col0 + bc);
        cp16(&Bs[st][br + 8][bc],  W + (size_t)(kb + br + 8) * NOUT + col0 + bc);
    };

    const int fr = lane >> 2;          // fragment row / B col
    const int fc = lane & 3;           // fragment k col

    auto COMPUTE = [&](int buf) {
        #pragma unroll
        for (int ks = 0; ks < 2; ++ks) {
            const int kk = ks * 8;
            unsigned af[4][4], bf[4][2];
            #pragma unroll
            for (int mi = 0; mi < 4; mi++) {
                const int rb = wm * 64 + mi * 16;
                af[mi][0] = f2tf(As[buf][rb + fr][kk + fc]);
                af[mi][1] = f2tf(As[buf][rb + fr + 8][kk + fc]);
                af[mi][2] = f2tf(As[buf][rb + fr][kk + fc + 4]);
                af[mi][3] = f2tf(As[buf][rb + fr + 8][kk + fc + 4]);
            }
            #pragma unroll
            for (int ni = 0; ni < 4; ni++) {
                const int cb = wn * 32 + ni * 8 + fr;
                bf[ni][0] = f2tf(Bs[buf][kk + fc][cb]);
                bf[ni][1] = f2tf(Bs[buf][kk + fc + 4][cb]);
            }
            #pragma unroll
            for (int mi = 0; mi < 4; mi++)
                #pragma unroll
                for (int ni = 0; ni < 4; ni++)
                    mma_tf32(acc[mi][ni], af[mi], bf[ni]);
        }
    };

    // prologue: issue STAGES-1 groups
    #pragma unroll
    for (int s = 0; s < STAGES - 1; ++s) {
        ISSUE(s, s);
        cp_commit();
    }

    for (int it = 0; it < NIT; ++it) {
        cp_wait<STAGES - 2>();         // group `it` complete (one group committed per iter)
        __syncthreads();               // all warps done with stage (it-1)%STAGES
        const int nx = it + STAGES - 1;
        if (nx < NIT) ISSUE(nx, nx % STAGES);
        cp_commit();                   // always commit (empty groups keep the count aligned)
        COMPUTE(it % STAGES);
    }

    // epilogue: bias -> ReLU -> BatchNorm(eval)
    float sc[4][2], sh[4][2], bb[4][2];
    int   cbs[4];
    #pragma unroll
    for (int ni = 0; ni < 4; ni++) {
        const int cb = col0 + wn * 32 + ni * 8 + ((lane & 3) << 1);
        cbs[ni] = cb;
        #pragma unroll
        for (int j = 0; j < 2; j++) {
            const int c = cb + j;
            const float rs = rsqrtf(var[c] + EPSBN);
            sc[ni][j] = gam[c] * rs;
            sh[ni][j] = bet[c] - mu[c] * sc[ni][j];
            bb[ni][j] = bias[c];
        }
    }
    #pragma unroll
    for (int mi = 0; mi < 4; mi++) {
        const int rbase = row0 + wm * 64 + mi * 16 + (lane >> 2);
        #pragma unroll
        for (int h = 0; h < 2; h++) {
            const int r = rbase + h * 8;
            if (r < M) {
                #pragma unroll
                for (int ni = 0; ni < 4; ni++) {
                    float z0 = acc[mi][ni][h * 2 + 0] + bb[ni][0];
                    float z1 = acc[mi][ni][h * 2 + 1] + bb[ni][1];
                    z0 = fmaxf(z0, 0.0f);
                    z1 = fmaxf(z1, 0.0f);
                    float2 o;
                    o.x = z0 * sc[ni][0] + sh[ni][0];
                    o.y = z1 * sc[ni][1] + sh[ni][1];
                    *(float2*)(C + (size_t)r * NOUT + cbs[ni]) = o;
                }
            }
        }
    }
}

// ---------------- launcher ---------------------------------------------------
extern "C" void kernel_launch(void* const* d_in, const int* in_sizes, int n_in,
                              void* d_out, int out_size) {
    const float* x   = (const float*)d_in[0];
    const int*   ei  = (const int*)d_in[1];
    const int    E   = in_sizes[1] / 2;
    const int    M   = in_sizes[0] / 128;
    const int*   src = ei;
    const int*   dst = ei + E;

    const float* w1l = (const float*)d_in[2];
    const float* w1r = (const float*)d_in[3];
    const float* b1  = (const float*)d_in[4];
    const float* ga1 = (const float*)d_in[5];
    const float* be1 = (const float*)d_in[6];
    const float* m1  = (const float*)d_in[7];
    const float* v1  = (const float*)d_in[8];
    const float* w2l = (const float*)d_in[9];
    const float* w2r = (const float*)d_in[10];
    const float* b2  = (const float*)d_in[11];
    const float* ga2 = (const float*)d_in[12];
    const float* be2 = (const float*)d_in[13];
    const float* m2  = (const float*)d_in[14];
    const float* v2  = (const float*)d_in[15];
    const float* w3l = (const float*)d_in[16];
    const float* w3r = (const float*)d_in[17];
    const float* b3  = (const float*)d_in[18];
    const float* ga3 = (const float*)d_in[19];
    const float* be3 = (const float*)d_in[20];
    const float* m3  = (const float*)d_in[21];
    const float* v3  = (const float*)d_in[22];

    float* out = (float*)d_out;

    float *agg, *h1, *h2;
    int   *cnt;
    cudaGetSymbolAddress((void**)&agg, g_agg);
    cudaGetSymbolAddress((void**)&h1,  g_h1);
    cudaGetSymbolAddress((void**)&h2,  g_h2);
    cudaGetSymbolAddress((void**)&cnt, g_cnt);

    const int T = 256;

    // ---- CSR build (dst-sorted adjacency) ----
    cudaMemsetAsync(cnt, 0, (size_t)M * sizeof(int), 0);
    hist_kernel<<<(E + T - 1) / T, T>>>(dst, E);
    scan_kernel<<<1, 1024>>>(M);
    fill_kernel<<<(E + T - 1) / T, T>>>(src, dst, E);

    const int gwarps = (M * 32 + T - 1) / T;   // one warp per node

    // ---- layer 1: x[*,128] -> h1[*,128]
    gather_kernel<128><<<gwarps, T>>>(x, agg, M);
    {
        dim3 grid((M + 127) / 128, 1);
        gemm_tc<128, 128><<<grid, T>>>(agg, x, w1l, w1r, b1, ga1, be1, m1, v1, h1, M);
    }

    // ---- layer 2: h1[*,128] -> h2[*,256]
    gather_kernel<128><<<gwarps, T>>>(h1, agg, M);
    {
        dim3 grid((M + 127) / 128, 2);
        gemm_tc<128, 256><<<grid, T>>>(agg, h1, w2l, w2r, b2, ga2, be2, m2, v2, h2, M);
    }

    // ---- layer 3: h2[*,256] -> out[*,256]
    gather_kernel<256><<<gwarps, T>>>(h2, agg, M);
    {
        dim3 grid((M + 127) / 128, 2);
        gemm_tc<256, 256><<<grid, T>>>(agg, h2, w3l, w3r, b3, ga3, be3, m3, v3, out, M);
    }
}

// round 11
// speedup vs baseline: 2.4883x; 1.0224x over previous
#include <cuda_runtime.h>
#include <math.h>
#include <stdint.h>

#define NMAX 100000
#define EMAX 2000000
#define EPSBN 1e-5f

// ---------------- scratch (device globals: no allocations allowed) ----------
__device__ float g_agg[(size_t)NMAX * 256];   // aggregation buffer (tf32-rounded)
__device__ float g_h1[(size_t)NMAX * 128];    // layer-1 output (tf32-rounded)
__device__ float g_h2[(size_t)NMAX * 256];    // layer-2 output (tf32-rounded)
__device__ float g_xr[(size_t)NMAX * 128];    // tf32-rounded copy of x
__device__ float g_wr[229376];                // tf32-rounded weights ([K][N] layout)
__device__ int   g_cnt[NMAX];
__device__ int   g_off[NMAX + 1];
__device__ int   g_cur[NMAX];
__device__ int   g_csr[EMAX];
__device__ float g_invdeg[NMAX];

// ---------------- helpers -----------------------------------------------------
__device__ __forceinline__ unsigned f2tf(float f) {
    unsigned u;
    asm("cvt.rna.tf32.f32 %0, %1;" : "=r"(u) : "f"(f));
    return u;
}
__device__ __forceinline__ float tf32r(float f) { return __uint_as_float(f2tf(f)); }

__device__ __forceinline__ void mma_tf32(float* c, const unsigned* a, const unsigned* b) {
    asm volatile(
        "mma.sync.aligned.m16n8k8.row.col.f32.tf32.tf32.f32 "
        "{%0,%1,%2,%3}, {%4,%5,%6,%7}, {%8,%9}, {%0,%1,%2,%3};"
        : "+f"(c[0]), "+f"(c[1]), "+f"(c[2]), "+f"(c[3])
        : "r"(a[0]), "r"(a[1]), "r"(a[2]), "r"(a[3]), "r"(b[0]), "r"(b[1]));
}

__device__ __forceinline__ void cp16(void* dst, const void* src) {
    unsigned d = (unsigned)__cvta_generic_to_shared(dst);
    asm volatile("cp.async.cg.shared.global [%0], [%1], 16;" :: "r"(d), "l"(src));
}
__device__ __forceinline__ void cp_commit() { asm volatile("cp.async.commit_group;"); }
template<int N>
__device__ __forceinline__ void cp_wait() { asm volatile("cp.async.wait_group %0;" :: "n"(N)); }

// ---------------- CSR build --------------------------------------------------
__global__ void hist_kernel(const int* __restrict__ dst, int E) {
    int i = blockIdx.x * blockDim.x + threadIdx.x;
    if (i < E) atomicAdd(&g_cnt[dst[i]], 1);
}

__global__ void scan_kernel(int M) {
    __shared__ int part[1024];
    const int t = threadIdx.x;
    const int chunk = (M + 1023) >> 10;
    const int beg = t * chunk;
    const int end = min(beg + chunk, M);
    int s = 0;
    for (int i = beg; i < end; i++) s += g_cnt[i];
    part[t] = s;
    __syncthreads();
    for (int ofs = 1; ofs < 1024; ofs <<= 1) {
        int v = (t >= ofs) ? part[t - ofs] : 0;
        __syncthreads();
        part[t] += v;
        __syncthreads();
    }
    int run = (t > 0) ? part[t - 1] : 0;
    for (int i = beg; i < end; i++) {
        g_off[i] = run;
        g_cur[i] = run;
        g_invdeg[i] = 1.0f / fmaxf((float)g_cnt[i], 1.0f);
        run += g_cnt[i];
    }
    if (end == M) g_off[M] = run;
}

__global__ void fill_kernel(const int* __restrict__ src,
                            const int* __restrict__ dst, int E) {
    int i = blockIdx.x * blockDim.x + threadIdx.x;
    if (i < E) {
        int d = dst[i];
        int pos = atomicAdd(&g_cur[d], 1);
        g_csr[pos] = src[i];
    }
}

// ---------------- setup: tf32-rounded copies ---------------------------------
__global__ void round_copy(const float* __restrict__ in, float* __restrict__ out, int n) {
    int i = blockIdx.x * blockDim.x + threadIdx.x;
    if (i < n) out[i] = tf32r(in[i]);
}

__global__ void prep_weights(const float* __restrict__ w1l, const float* __restrict__ w1r,
                             const float* __restrict__ w2l, const float* __restrict__ w2r,
                             const float* __restrict__ w3l, const float* __restrict__ w3r) {
    const int seg = blockIdx.y;
    const float* src;
    float* dst;
    int n;
    switch (seg) {
        case 0:  src = w1l; dst = g_wr + 0;      n = 16384; break;
        case 1:  src = w1r; dst = g_wr + 16384;  n = 16384; break;
        case 2:  src = w2l; dst = g_wr + 32768;  n = 32768; break;
        case 3:  src = w2r; dst = g_wr + 65536;  n = 32768; break;
        case 4:  src = w3l; dst = g_wr + 98304;  n = 65536; break;
        default: src = w3r; dst = g_wr + 163840; n = 65536; break;
    }
    int i = blockIdx.x * blockDim.x + threadIdx.x;
    if (i < n) dst[i] = tf32r(src[i]);   // same [K][NOUT] layout, rounded
}

// ---------------- CSR gather: agg[n,:] = round_tf32(mean h[src,:]) -----------
template<int D>
__global__ void gather_kernel(const float* __restrict__ h,
                              float* __restrict__ agg, int M) {
    const int warp = (blockIdx.x * blockDim.x + threadIdx.x) >> 5;
    const int lane = threadIdx.x & 31;
    if (warp >= M) return;
    const int beg = g_off[warp];
    const int end = g_off[warp + 1];

    float4 a0 = make_float4(0.f, 0.f, 0.f, 0.f);
    float4 a1 = make_float4(0.f, 0.f, 0.f, 0.f);

    for (int j0 = beg; j0 < end; j0 += 32) {
        const int myi = (j0 + lane < end) ? g_csr[j0 + lane] : 0;
        const int cnt = min(32, end - j0);
        for (int t = 0; t < cnt; t++) {
            const int s = __shfl_sync(0xffffffffu, myi, t);
            const float4* row = (const float4*)(h + (size_t)s * D);
            const float4 v = row[lane];
            a0.x += v.x; a0.y += v.y; a0.z += v.z; a0.w += v.w;
            if (D == 256) {
                const float4 w = row[lane + 32];
                a1.x += w.x; a1.y += w.y; a1.z += w.z; a1.w += w.w;
            }
        }
    }
    const float s = g_invdeg[warp];
    float4* outr = (float4*)(agg + (size_t)warp * D);
    outr[lane] = make_float4(tf32r(a0.x * s), tf32r(a0.y * s),
                             tf32r(a0.z * s), tf32r(a0.w * s));
    if (D == 256) {
        outr[lane + 32] = make_float4(tf32r(a1.x * s), tf32r(a1.y * s),
                                      tf32r(a1.z * s), tf32r(a1.w * s));
    }
}

// ---------------- fused dual GEMM (mma.sync, pre-rounded) + bias/ReLU/BN -----
// C = BN(ReLU( Aagg @ Wl + Aself @ Wr + bias ));  inputs already tf32-rounded.
// Block 128x128, 128 threads (4 warps, 2x2), warp tile 64x64, BK=16, 4 stages.
#define STAGES 4
#define A_PITCH 20
#define B_PITCH 136
#define A_STRIDE (128 * A_PITCH)            // floats per A stage
#define B_STRIDE (16 * B_PITCH)             // floats per B stage
#define GEMM_SMEM ((STAGES * (A_STRIDE + B_STRIDE)) * 4)

template<int K, int NOUT>
__global__ void __launch_bounds__(128)
gemm_tc(const float* __restrict__ Aagg,
        const float* __restrict__ Aself,
        const float* __restrict__ Wl,
        const float* __restrict__ Wr,
        const float* __restrict__ bias,
        const float* __restrict__ gam,
        const float* __restrict__ bet,
        const float* __restrict__ mu,
        const float* __restrict__ var,
        float* __restrict__ C, int M, int round_out) {
    extern __shared__ float sm[];
    float* As = sm;                          // [STAGES][128][A_PITCH]
    float* Bs = sm + STAGES * A_STRIDE;      // [STAGES][16][B_PITCH]

    const int tid  = threadIdx.x;
    const int lane = tid & 31;
    const int wid  = tid >> 5;
    const int wm   = wid & 1;           // warp row (0..1) -> 64 rows
    const int wn   = wid >> 1;          // warp col (0..1) -> 64 cols
    const int row0 = blockIdx.x * 128;
    const int col0 = blockIdx.y * 128;

    // cp.async load mappings (128 threads, 4 x 16B each for A and B)
    // A tile 128x16: float4 idx = i*128+tid -> row idx>>2, col (idx&3)*4
    // B tile 16x128: float4 idx -> row idx>>5, col (idx&31)*4
    const int gr[4] = { min(row0 + ((0 * 128 + tid) >> 2), M - 1),
                        min(row0 + ((1 * 128 + tid) >> 2), M - 1),
                        min(row0 + ((2 * 128 + tid) >> 2), M - 1),
                        min(row0 + ((3 * 128 + tid) >> 2), M - 1) };

    float acc[4][8][4];
    #pragma unroll
    for (int i = 0; i < 4; i++)
        #pragma unroll
        for (int j = 0; j < 8; j++)
            #pragma unroll
            for (int q = 0; q < 4; q++) acc[i][j][q] = 0.0f;

    const int PH  = K / 16;
    const int NIT = 2 * PH;

    auto ISSUE = [&](int it, int st) {
        const int ph = (it >= PH) ? 1 : 0;
        const int kb = (ph ? it - PH : it) * 16;
        const float* A = ph ? Aself : Aagg;
        const float* W = ph ? Wr : Wl;
        float* as = As + st * A_STRIDE;
        float* bs = Bs + st * B_STRIDE;
        #pragma unroll
        for (int i = 0; i < 4; i++) {
            const int idx = i * 128 + tid;
            const int arr = idx >> 2, acc_ = (idx & 3) << 2;
            cp16(as + arr * A_PITCH + acc_, A + (size_t)gr[i] * K + kb + acc_);
            const int brr = idx >> 5, bcc = (idx & 31) << 2;
            cp16(bs + brr * B_PITCH + bcc, W + (size_t)(kb + brr) * NOUT + col0 + bcc);
        }
    };

    const int fr = lane >> 2;           // fragment row / B col
    const int fc = lane & 3;            // fragment k col

    auto COMPUTE = [&](int st) {
        const float* as = As + st * A_STRIDE;
        const float* bs = Bs + st * B_STRIDE;
        #pragma unroll
        for (int ks = 0; ks < 2; ++ks) {
            const int kk = ks * 8;
            unsigned af[4][4], bf[8][2];
            #pragma unroll
            for (int mi = 0; mi < 4; mi++) {
                const int rb = wm * 64 + mi * 16;
                af[mi][0] = __float_as_uint(as[(rb + fr)     * A_PITCH + kk + fc]);
                af[mi][1] = __float_as_uint(as[(rb + fr + 8) * A_PITCH + kk + fc]);
                af[mi][2] = __float_as_uint(as[(rb + fr)     * A_PITCH + kk + fc + 4]);
                af[mi][3] = __float_as_uint(as[(rb + fr + 8) * A_PITCH + kk + fc + 4]);
            }
            #pragma unroll
            for (int ni = 0; ni < 8; ni++) {
                const int cb = wn * 64 + ni * 8 + fr;
                bf[ni][0] = __float_as_uint(bs[(kk + fc)     * B_PITCH + cb]);
                bf[ni][1] = __float_as_uint(bs[(kk + fc + 4) * B_PITCH + cb]);
            }
            #pragma unroll
            for (int mi = 0; mi < 4; mi++)
                #pragma unroll
                for (int ni = 0; ni < 8; ni++)
                    mma_tf32(acc[mi][ni], af[mi], bf[ni]);
        }
    };

    #pragma unroll
    for (int s = 0; s < STAGES - 1; ++s) {
        ISSUE(s, s);
        cp_commit();
    }

    for (int it = 0; it < NIT; ++it) {
        cp_wait<STAGES - 2>();
        __syncthreads();
        const int nx = it + STAGES - 1;
        if (nx < NIT) ISSUE(nx, nx % STAGES);
        cp_commit();
        COMPUTE(it % STAGES);
    }

    // epilogue: bias -> ReLU -> BatchNorm(eval), optional tf32 rounding
    float sc[8][2], sh[8][2], bb[8][2];
    int   cbs[8];
    #pragma unroll
    for (int ni = 0; ni < 8; ni++) {
        const int cb = col0 + wn * 64 + ni * 8 + ((lane & 3) << 1);
        cbs[ni] = cb;
        #pragma unroll
        for (int j = 0; j < 2; j++) {
            const int c = cb + j;
            const float rs = rsqrtf(var[c] + EPSBN);
            sc[ni][j] = gam[c] * rs;
            sh[ni][j] = bet[c] - mu[c] * sc[ni][j];
            bb[ni][j] = bias[c];
        }
    }
    #pragma unroll
    for (int mi = 0; mi < 4; mi++) {
        const int rbase = row0 + wm * 64 + mi * 16 + (lane >> 2);
        #pragma unroll
        for (int h = 0; h < 2; h++) {
            const int r = rbase + h * 8;
            if (r < M) {
                #pragma unroll
                for (int ni = 0; ni < 8; ni++) {
                    float z0 = acc[mi][ni][h * 2 + 0] + bb[ni][0];
                    float z1 = acc[mi][ni][h * 2 + 1] + bb[ni][1];
                    z0 = fmaxf(z0, 0.0f) * sc[ni][0] + sh[ni][0];
                    z1 = fmaxf(z1, 0.0f) * sc[ni][1] + sh[ni][1];
                    float2 o;
                    o.x = round_out ? tf32r(z0) : z0;
                    o.y = round_out ? tf32r(z1) : z1;
                    *(float2*)(C + (size_t)r * NOUT + cbs[ni]) = o;
                }
            }
        }
    }
}

// ---------------- launcher ---------------------------------------------------
extern "C" void kernel_launch(void* const* d_in, const int* in_sizes, int n_in,
                              void* d_out, int out_size) {
    const float* x   = (const float*)d_in[0];
    const int*   ei  = (const int*)d_in[1];
    const int    E   = in_sizes[1] / 2;
    const int    M   = in_sizes[0] / 128;
    const int*   src = ei;
    const int*   dst = ei + E;

    const float* w1l = (const float*)d_in[2];
    const float* w1r = (const float*)d_in[3];
    const float* b1  = (const float*)d_in[4];
    const float* ga1 = (const float*)d_in[5];
    const float* be1 = (const float*)d_in[6];
    const float* m1  = (const float*)d_in[7];
    const float* v1  = (const float*)d_in[8];
    const float* w2l = (const float*)d_in[9];
    const float* w2r = (const float*)d_in[10];
    const float* b2  = (const float*)d_in[11];
    const float* ga2 = (const float*)d_in[12];
    const float* be2 = (const float*)d_in[13];
    const float* m2  = (const float*)d_in[14];
    const float* v2  = (const float*)d_in[15];
    const float* w3l = (const float*)d_in[16];
    const float* w3r = (const float*)d_in[17];
    const float* b3  = (const float*)d_in[18];
    const float* ga3 = (const float*)d_in[19];
    const float* be3 = (const float*)d_in[20];
    const float* m3  = (const float*)d_in[21];
    const float* v3  = (const float*)d_in[22];

    float* out = (float*)d_out;

    float *agg, *h1, *h2, *xr, *wr;
    int   *cnt;
    cudaGetSymbolAddress((void**)&agg, g_agg);
    cudaGetSymbolAddress((void**)&h1,  g_h1);
    cudaGetSymbolAddress((void**)&h2,  g_h2);
    cudaGetSymbolAddress((void**)&xr,  g_xr);
    cudaGetSymbolAddress((void**)&wr,  g_wr);
    cudaGetSymbolAddress((void**)&cnt, g_cnt);

    cudaFuncSetAttribute(gemm_tc<128, 128>, cudaFuncAttributeMaxDynamicSharedMemorySize, GEMM_SMEM);
    cudaFuncSetAttribute(gemm_tc<128, 256>, cudaFuncAttributeMaxDynamicSharedMemorySize, GEMM_SMEM);
    cudaFuncSetAttribute(gemm_tc<256, 256>, cudaFuncAttributeMaxDynamicSharedMemorySize, GEMM_SMEM);

    const int T = 256;

    // ---- CSR build + rounded copies ----
    cudaMemsetAsync(cnt, 0, (size_t)M * sizeof(int), 0);
    hist_kernel<<<(E + T - 1) / T, T>>>(dst, E);
    scan_kernel<<<1, 1024>>>(M);
    fill_kernel<<<(E + T - 1) / T, T>>>(src, dst, E);
    round_copy<<<(M * 128 + T - 1) / T, T>>>(x, xr, M * 128);
    {
        dim3 g(256, 6);
        prep_weights<<<g, T>>>(w1l, w1r, w2l, w2r, w3l, w3r);
    }

    const int gwarps = (M * 32 + T - 1) / T;   // one warp per node
    const int rtiles = (M + 127) / 128;

    // ---- layer 1: x[*,128] -> h1[*,128]
    gather_kernel<128><<<gwarps, T>>>(x, agg, M);
    gemm_tc<128, 128><<<dim3(rtiles, 1), 128, GEMM_SMEM>>>(
        agg, xr, wr + 0, wr + 16384, b1, ga1, be1, m1, v1, h1, M, 1);

    // ---- layer 2: h1[*,128] -> h2[*,256]
    gather_kernel<128><<<gwarps, T>>>(h1, agg, M);
    gemm_tc<128, 256><<<dim3(rtiles, 2), 128, GEMM_SMEM>>>(
        agg, h1, wr + 32768, wr + 65536, b2, ga2, be2, m2, v2, h2, M, 1);

    // ---- layer 3: h2[*,256] -> out[*,256]
    gather_kernel<256><<<gwarps, T>>>(h2, agg, M);
    gemm_tc<256, 256><<<dim3(rtiles, 2), 128, GEMM_SMEM>>>(
        agg, h2, wr + 98304, wr + 163840, b3, ga3, be3, m3, v3, out, M, 0);
}